// round 1
// baseline (speedup 1.0000x reference)
#include <cuda_runtime.h>

#define SZ   256          // image size
#define NT   256          // number of triangles
#define REC  28           // floats per triangle record (16B aligned: 28*4=112)

// Per-triangle record layout (floats):
//  0..3  : pAB edge: ax(=v1x), ay(=v1y), dy(=v0y-v1y), dx(=v0x-v1x)
//  4..7  : pCB edge: ax(=v2x), ay(=v2y), dy(=v1y-v2y), dx(=v1x-v2x)
//  8..11 : pCA edge: ax(=v0x), ay(=v0y), dy(=v2y-v0y), dx(=v2x-v0x)
//  12    : invw = 1/ws
//  13..15: z0, z1, z2
//  16..21: u0,v0,u1,v1,u2,v2  (uvs*2-1)
//  22..25: bbox xmin,xmax,ymin,ymax  (xmin=+1e30 when triangle invalid)
//  26..27: pad

__device__ float g_tri[NT * REC];
__device__ float g_zmin;

__global__ void prep_kernel(const float* __restrict__ tris,
                            const float* __restrict__ uvs) {
    int t = threadIdx.x;
    const float* T = tris + t * 9;
    float v0x = T[0], v0y = T[1], v0z = T[2];
    float v1x = T[3], v1y = T[4], v1z = T[5];
    float v2x = T[6], v2y = T[7], v2z = T[8];

    float w = (v1x - v0x) * (v2y - v0y) - (v1y - v0y) * (v2x - v0x);
    bool valid = (w >= 1e-9f);
    float ws = valid ? w : 1.0f;
    float invw = 1.0f / ws;

    float* R = g_tri + t * REC;
    R[0] = v1x;  R[1] = v1y;  R[2]  = v0y - v1y;  R[3]  = v0x - v1x;
    R[4] = v2x;  R[5] = v2y;  R[6]  = v1y - v2y;  R[7]  = v1x - v2x;
    R[8] = v0x;  R[9] = v0y;  R[10] = v2y - v0y;  R[11] = v2x - v0x;
    R[12] = invw;
    R[13] = v0z; R[14] = v1z; R[15] = v2z;

    const float* U = uvs + t * 6;
    R[16] = U[0] * 2.0f - 1.0f;  R[17] = U[1] * 2.0f - 1.0f;
    R[18] = U[2] * 2.0f - 1.0f;  R[19] = U[3] * 2.0f - 1.0f;
    R[20] = U[4] * 2.0f - 1.0f;  R[21] = U[5] * 2.0f - 1.0f;

    float xmin = fminf(v0x, fminf(v1x, v2x));
    float xmax = fmaxf(v0x, fmaxf(v1x, v2x));
    float ymin = fminf(v0y, fminf(v1y, v2y));
    float ymax = fmaxf(v0y, fmaxf(v1y, v2y));
    R[22] = valid ? xmin : 1e30f;
    R[23] = xmax;
    R[24] = ymin;
    R[25] = ymax;
    R[26] = 0.0f; R[27] = 0.0f;

    // global zmin over all vertices
    __shared__ float sz[NT];
    sz[t] = fminf(v0z, fminf(v1z, v2z));
    __syncthreads();
    for (int s = NT / 2; s > 0; s >>= 1) {
        if (t < s) sz[t] = fminf(sz[t], sz[t + s]);
        __syncthreads();
    }
    if (t == 0) g_zmin = sz[0];
}

// Block: 32x8 threads => 32x8 pixel tile. Grid: (256/32, 256/8) = (8, 32).
__global__ __launch_bounds__(256)
void render_kernel(const float* __restrict__ uvmap, float* __restrict__ out) {
    __shared__ __align__(16) float s_tri[NT * REC];   // 28 KB
    __shared__ unsigned short s_list[NT];
    __shared__ int s_wcnt[8];

    int tid = threadIdx.y * 32 + threadIdx.x;

    // Stage all triangle records into shared memory
    const float4* gsrc = (const float4*)g_tri;
    float4* sdst = (float4*)s_tri;
    #pragma unroll
    for (int k = tid; k < NT * REC / 4; k += 256) sdst[k] = gsrc[k];
    __syncthreads();

    // Pixel coordinates: pts[i][j] = (lin[j], lin[255-i]), lin[k] = -1 + k*2/255
    const float d = 2.0f / 255.0f;
    int j = blockIdx.x * 32 + threadIdx.x;
    int i = blockIdx.y * 8  + threadIdx.y;
    float px = -1.0f + (float)j * d;
    float py =  1.0f - (float)i * d;

    // Tile extents for culling
    float txmin = -1.0f + (float)(blockIdx.x * 32) * d;
    float txmax = -1.0f + (float)(blockIdx.x * 32 + 31) * d;
    float tymax =  1.0f - (float)(blockIdx.y * 8) * d;
    float tymin =  1.0f - (float)(blockIdx.y * 8 + 7) * d;

    // Order-preserving stream compaction of triangles overlapping this tile
    {
        const float* R = s_tri + tid * REC;
        bool keep = (R[22] <= txmax) && (R[23] >= txmin) &&
                    (R[24] <= tymax) && (R[25] >= tymin);
        unsigned mask = __ballot_sync(0xffffffffu, keep);
        int warp = tid >> 5, lane = tid & 31;
        if (lane == 0) s_wcnt[warp] = __popc(mask);
        __syncthreads();
        int base = 0;
        #pragma unroll
        for (int w = 0; w < 8; w++) if (w < warp) base += s_wcnt[w];
        if (keep) s_list[base + __popc(mask & ((1u << lane) - 1u))] = (unsigned short)tid;
    }
    int cnt = 0;
    #pragma unroll
    for (int w = 0; w < 8; w++) cnt += s_wcnt[w];
    __syncthreads();

    // Per-pixel sequential scan over surviving triangles (order preserved)
    float zb = g_zmin;
    float uu = 0.0f, vv = 0.0f;
    bool cov = false;

    for (int k = 0; k < cnt; k++) {
        int tt = s_list[k];
        const float4* Q = (const float4*)(s_tri + tt * REC);
        float4 q0 = Q[0], q1 = Q[1], q2 = Q[2];

        float pAB = (px - q0.x) * q0.z - (py - q0.y) * q0.w;
        float pCB = (px - q1.x) * q1.z - (py - q1.y) * q1.w;
        float pCA = (px - q2.x) * q2.z - (py - q2.y) * q2.w;

        bool inside = (fmaxf(pAB, 0.0f) * fmaxf(pCB, 0.0f) * fmaxf(pCA, 0.0f)) > 0.0f;
        if (inside) {
            float4 q3 = Q[3];                 // invw, z0, z1, z2
            float w1 = pCB * q3.x;
            float w2 = pCA * q3.x;
            float w3 = 1.0f - w1 - w2;
            float z = w1 * q3.y + w2 * q3.z + w3 * q3.w;
            if (z >= zb) {
                zb = z;
                float4 q4 = Q[4];             // u0,v0,u1,v1
                float4 q5 = Q[5];             // u2,v2,-,-
                uu = w1 * q4.x + w2 * q4.z + w3 * q5.x;
                vv = w1 * q4.y + w2 * q4.w + w3 * q5.y;
                cov = true;
            }
        }
    }

    // Deferred bilinear texture sample for the winning triangle only
    float r = 0.0f, g = 0.0f, b = 0.0f, a = 0.0f;
    if (cov) {
        a = 1.0f;
        float x = (uu + 1.0f) * 0.5f * 1023.0f;
        float y = (vv + 1.0f) * 0.5f * 1023.0f;
        float x0f = floorf(x);
        float y0f = floorf(y);
        float wx = x - x0f;
        float wy = y - y0f;
        #pragma unroll
        for (int cy = 0; cy < 2; cy++) {
            #pragma unroll
            for (int cx = 0; cx < 2; cx++) {
                float ix = x0f + (float)cx;
                float iy = y0f + (float)cy;
                bool inb = (ix >= 0.0f) && (ix <= 1023.0f) &&
                           (iy >= 0.0f) && (iy <= 1023.0f);
                if (inb) {
                    int ii = (int)ix;
                    int jj = (int)iy;
                    float wgt = (cx ? wx : 1.0f - wx) * (cy ? wy : 1.0f - wy);
                    int off = jj * 1024 + ii;
                    r += __ldg(uvmap + off) * wgt;
                    g += __ldg(uvmap + 1048576 + off) * wgt;
                    b += __ldg(uvmap + 2097152 + off) * wgt;
                }
            }
        }
    }

    int pix = i * SZ + j;
    out[pix]              = r;
    out[65536 + pix]      = g;
    out[2 * 65536 + pix]  = b;
    out[3 * 65536 + pix]  = a;
}

extern "C" void kernel_launch(void* const* d_in, const int* in_sizes, int n_in,
                              void* d_out, int out_size) {
    const float* tris  = (const float*)d_in[0];   // (256,3,3)
    const float* uvs   = (const float*)d_in[1];   // (256,3,2)
    const float* uvmap = (const float*)d_in[2];   // (3,1024,1024)
    float* out = (float*)d_out;                   // (4,256,256)

    prep_kernel<<<1, NT>>>(tris, uvs);
    dim3 block(32, 8);
    dim3 grid(SZ / 32, SZ / 8);
    render_kernel<<<grid, block>>>(uvmap, out);
}

// round 2
// speedup vs baseline: 1.4196x; 1.4196x over previous
#include <cuda_runtime.h>

#define SZ   256          // image size
#define NT   256          // number of triangles
#define REC  28           // floats per triangle record (16B aligned: 28*4=112)

// Per-triangle record layout (floats):
//  0..3  : pAB edge: ax(=v1x), ay(=v1y), dy(=v0y-v1y), dx(=v0x-v1x)
//  4..7  : pCB edge: ax(=v2x), ay(=v2y), dy(=v1y-v2y), dx(=v1x-v2x)
//  8..11 : pCA edge: ax(=v0x), ay(=v0y), dy(=v2y-v0y), dx(=v2x-v0x)
//  12    : invw = 1/ws
//  13..15: z0, z1, z2
//  16..21: u0,v0,u1,v1,u2,v2  (uvs*2-1)
//  22..25: bbox xmin,xmax,ymin,ymax  (xmin=+1e30 when triangle invalid)
//  26..27: pad

__device__ float g_tri[NT * REC];
__device__ float g_zmin;

__global__ void prep_kernel(const float* __restrict__ tris,
                            const float* __restrict__ uvs) {
    int t = threadIdx.x;
    const float* T = tris + t * 9;
    float v0x = T[0], v0y = T[1], v0z = T[2];
    float v1x = T[3], v1y = T[4], v1z = T[5];
    float v2x = T[6], v2y = T[7], v2z = T[8];

    float w = (v1x - v0x) * (v2y - v0y) - (v1y - v0y) * (v2x - v0x);
    bool valid = (w >= 1e-9f);
    float ws = valid ? w : 1.0f;
    float invw = 1.0f / ws;

    float* R = g_tri + t * REC;
    R[0] = v1x;  R[1] = v1y;  R[2]  = v0y - v1y;  R[3]  = v0x - v1x;
    R[4] = v2x;  R[5] = v2y;  R[6]  = v1y - v2y;  R[7]  = v1x - v2x;
    R[8] = v0x;  R[9] = v0y;  R[10] = v2y - v0y;  R[11] = v2x - v0x;
    R[12] = invw;
    R[13] = v0z; R[14] = v1z; R[15] = v2z;

    const float* U = uvs + t * 6;
    R[16] = U[0] * 2.0f - 1.0f;  R[17] = U[1] * 2.0f - 1.0f;
    R[18] = U[2] * 2.0f - 1.0f;  R[19] = U[3] * 2.0f - 1.0f;
    R[20] = U[4] * 2.0f - 1.0f;  R[21] = U[5] * 2.0f - 1.0f;

    float xmin = fminf(v0x, fminf(v1x, v2x));
    float xmax = fmaxf(v0x, fmaxf(v1x, v2x));
    float ymin = fminf(v0y, fminf(v1y, v2y));
    float ymax = fmaxf(v0y, fmaxf(v1y, v2y));
    R[22] = valid ? xmin : 1e30f;
    R[23] = xmax;
    R[24] = ymin;
    R[25] = ymax;
    R[26] = 0.0f; R[27] = 0.0f;

    // global zmin over all vertices
    __shared__ float sz[NT];
    sz[t] = fminf(v0z, fminf(v1z, v2z));
    __syncthreads();
    for (int s = NT / 2; s > 0; s >>= 1) {
        if (t < s) sz[t] = fminf(sz[t], sz[t + s]);
        __syncthreads();
    }
    if (t == 0) g_zmin = sz[0];
}

// Block: 256 threads = 64 pixels (8x8 tile) x 4 triangle slices.
// Warp layout: lane = slice*8 + pixCol, warp index = pixRow within tile.
// Grid: (256/8, 256/8) = (32, 32) = 1024 blocks.
//
// Correctness of the split: 'inside' implies all barycentric weights > 0, so
// interpolated z is a convex combination of the triangle's vertex z's, hence
// >= global zmin (the zbuf init). The sequential scan therefore reduces to
// argmax over covering triangles (ties -> later index), which is
// order-independent and can be computed in disjoint slices then merged.
__global__ __launch_bounds__(256)
void render_kernel(const float* __restrict__ uvmap, float* __restrict__ out) {
    __shared__ __align__(16) float s_tri[NT * REC];   // 28 KB
    __shared__ unsigned short s_list[NT];
    __shared__ int s_wcnt[8];

    int tid   = threadIdx.x;
    int warp  = tid >> 5;
    int lane  = tid & 31;
    int slice = lane >> 3;        // 0..3
    int pcol  = lane & 7;         // 0..7

    // Stage all triangle records into shared memory
    const float4* gsrc = (const float4*)g_tri;
    float4* sdst = (float4*)s_tri;
    #pragma unroll
    for (int k = tid; k < NT * REC / 4; k += 256) sdst[k] = gsrc[k];
    __syncthreads();

    // Pixel coordinates: pts[i][j] = (lin[j], lin[255-i]), lin[k] = -1 + k*2/255
    const float d = 2.0f / 255.0f;
    int j = blockIdx.x * 8 + pcol;
    int i = blockIdx.y * 8 + warp;
    float px = -1.0f + (float)j * d;
    float py =  1.0f - (float)i * d;

    // Tile extents for culling (8x8 pixel tile)
    float txmin = -1.0f + (float)(blockIdx.x * 8) * d;
    float txmax = -1.0f + (float)(blockIdx.x * 8 + 7) * d;
    float tymax =  1.0f - (float)(blockIdx.y * 8) * d;
    float tymin =  1.0f - (float)(blockIdx.y * 8 + 7) * d;

    // Order-preserving stream compaction of triangles overlapping this tile
    {
        const float* R = s_tri + tid * REC;
        bool keep = (R[22] <= txmax) && (R[23] >= txmin) &&
                    (R[24] <= tymax) && (R[25] >= tymin);
        unsigned mask = __ballot_sync(0xffffffffu, keep);
        if (lane == 0) s_wcnt[warp] = __popc(mask);
        __syncthreads();
        int base = 0;
        #pragma unroll
        for (int w = 0; w < 8; w++) if (w < warp) base += s_wcnt[w];
        if (keep) s_list[base + __popc(mask & ((1u << lane) - 1u))] = (unsigned short)tid;
    }
    int cnt = 0;
    #pragma unroll
    for (int w = 0; w < 8; w++) cnt += s_wcnt[w];
    __syncthreads();

    // Each slice scans every 4th surviving triangle (argmax is order-free;
    // within a slice indices ascend so z>=zb keeps the later index on ties).
    float zb = g_zmin;
    float uu = 0.0f, vv = 0.0f;
    int   bi = -1;

    for (int k = slice; k < cnt; k += 4) {
        int tt = s_list[k];
        const float4* Q = (const float4*)(s_tri + tt * REC);
        float4 q0 = Q[0], q1 = Q[1], q2 = Q[2];

        float pAB = (px - q0.x) * q0.z - (py - q0.y) * q0.w;
        float pCB = (px - q1.x) * q1.z - (py - q1.y) * q1.w;
        float pCA = (px - q2.x) * q2.z - (py - q2.y) * q2.w;

        bool inside = (fmaxf(pAB, 0.0f) * fmaxf(pCB, 0.0f) * fmaxf(pCA, 0.0f)) > 0.0f;
        if (inside) {
            float4 q3 = Q[3];                 // invw, z0, z1, z2
            float w1 = pCB * q3.x;
            float w2 = pCA * q3.x;
            float w3 = 1.0f - w1 - w2;
            float z = w1 * q3.y + w2 * q3.z + w3 * q3.w;
            if (z >= zb) {
                zb = z;
                bi = tt;
                float4 q4 = Q[4];             // u0,v0,u1,v1
                float4 q5 = Q[5];             // u2,v2,-,-
                uu = w1 * q4.x + w2 * q4.z + w3 * q5.x;
                vv = w1 * q4.y + w2 * q4.w + w3 * q5.y;
            }
        }
    }

    // Merge the 4 slices of each pixel: (z, idx) max, ties -> larger idx.
    #pragma unroll
    for (int off = 8; off < 32; off <<= 1) {
        float oz = __shfl_down_sync(0xffffffffu, zb, off);
        int   oi = __shfl_down_sync(0xffffffffu, bi, off);
        float ou = __shfl_down_sync(0xffffffffu, uu, off);
        float ov = __shfl_down_sync(0xffffffffu, vv, off);
        bool take = (oz > zb) || ((oz == zb) && (oi > bi));
        if (take) { zb = oz; bi = oi; uu = ou; vv = ov; }
    }

    if (slice == 0) {
        // Deferred bilinear texture sample for the winning triangle only
        float r = 0.0f, g = 0.0f, b = 0.0f, a = 0.0f;
        if (bi >= 0) {
            a = 1.0f;
            float x = (uu + 1.0f) * 0.5f * 1023.0f;
            float y = (vv + 1.0f) * 0.5f * 1023.0f;
            float x0f = floorf(x);
            float y0f = floorf(y);
            float wx = x - x0f;
            float wy = y - y0f;
            #pragma unroll
            for (int cy = 0; cy < 2; cy++) {
                #pragma unroll
                for (int cx = 0; cx < 2; cx++) {
                    float ix = x0f + (float)cx;
                    float iy = y0f + (float)cy;
                    bool inb = (ix >= 0.0f) && (ix <= 1023.0f) &&
                               (iy >= 0.0f) && (iy <= 1023.0f);
                    if (inb) {
                        int ii = (int)ix;
                        int jj = (int)iy;
                        float wgt = (cx ? wx : 1.0f - wx) * (cy ? wy : 1.0f - wy);
                        int off = jj * 1024 + ii;
                        r += __ldg(uvmap + off) * wgt;
                        g += __ldg(uvmap + 1048576 + off) * wgt;
                        b += __ldg(uvmap + 2097152 + off) * wgt;
                    }
                }
            }
        }

        int pix = i * SZ + j;
        out[pix]              = r;
        out[65536 + pix]      = g;
        out[2 * 65536 + pix]  = b;
        out[3 * 65536 + pix]  = a;
    }
}

extern "C" void kernel_launch(void* const* d_in, const int* in_sizes, int n_in,
                              void* d_out, int out_size) {
    const float* tris  = (const float*)d_in[0];   // (256,3,3)
    const float* uvs   = (const float*)d_in[1];   // (256,3,2)
    const float* uvmap = (const float*)d_in[2];   // (3,1024,1024)
    float* out = (float*)d_out;                   // (4,256,256)

    prep_kernel<<<1, NT>>>(tris, uvs);
    dim3 block(256);
    dim3 grid(SZ / 8, SZ / 8);
    render_kernel<<<grid, block>>>(uvmap, out);
}

// round 3
// speedup vs baseline: 1.7813x; 1.2548x over previous
#include <cuda_runtime.h>

#define SZ   256          // image size
#define NT   256          // number of triangles
#define REC  24           // floats per triangle record (6 float4)

// Per-triangle record layout (float4 index):
//  q0 : pAB edge: ax(=v1x), ay(=v1y), dy(=v0y-v1y), dx(=v0x-v1x)
//  q1 : pCB edge: ax(=v2x), ay(=v2y), dy(=v1y-v2y), dx(=v1x-v2x)
//  q2 : pCA edge: ax(=v0x), ay(=v0y), dy(=v2y-v0y), dx(=v2x-v0x)
//  q3 : invw, z0, z1, z2
//  q4 : u0,v0,u1,v1   (uvs*2-1)
//  q5 : u2,v2,0,0

// Single fused kernel.
// Block: 256 threads = 64 pixels (8x8 tile) x 4 triangle slices.
// Warp layout: lane = slice*8 + pixCol, warp index = pixRow within tile.
// Grid: (256/8, 256/8) = (32, 32) = 1024 blocks.
//
// Correctness of the slice split: 'inside' implies all barycentric weights > 0,
// so interpolated z is a convex combination of the triangle's vertex z's, hence
// >= global zmin (the zbuf init). The sequential scan therefore reduces to
// argmax over covering triangles (ties -> later index), which is
// order-independent and can be computed in disjoint slices then merged.
__global__ __launch_bounds__(256)
void render_kernel(const float* __restrict__ tris,
                   const float* __restrict__ uvs,
                   const float* __restrict__ uvmap,
                   float* __restrict__ out) {
    __shared__ __align__(16) float4 s_q[NT * 6];      // 24 KB
    __shared__ unsigned short s_list[NT];
    __shared__ int s_wcnt[8];
    __shared__ float s_zred[8];

    int tid   = threadIdx.x;
    int warp  = tid >> 5;
    int lane  = tid & 31;
    int slice = lane >> 3;        // 0..3
    int pcol  = lane & 7;         // 0..7

    const float d = 2.0f / 255.0f;

    // Tile extents for culling (8x8 pixel tile)
    float txmin = -1.0f + (float)(blockIdx.x * 8) * d;
    float txmax = txmin + 7.0f * d;
    float tymax =  1.0f - (float)(blockIdx.y * 8) * d;
    float tymin = tymax - 7.0f * d;

    // ---- Fused prep: thread t builds triangle t's record in shared ----
    bool keep;
    float myzmin;
    {
        const float* T = tris + tid * 9;
        float v0x = __ldg(T + 0), v0y = __ldg(T + 1), v0z = __ldg(T + 2);
        float v1x = __ldg(T + 3), v1y = __ldg(T + 4), v1z = __ldg(T + 5);
        float v2x = __ldg(T + 6), v2y = __ldg(T + 7), v2z = __ldg(T + 8);

        float w = (v1x - v0x) * (v2y - v0y) - (v1y - v0y) * (v2x - v0x);
        bool valid = (w >= 1e-9f);
        float ws = valid ? w : 1.0f;
        float invw = 1.0f / ws;

        const float* U = uvs + tid * 6;
        float u0 = __ldg(U + 0) * 2.0f - 1.0f, uv0 = __ldg(U + 1) * 2.0f - 1.0f;
        float u1 = __ldg(U + 2) * 2.0f - 1.0f, uv1 = __ldg(U + 3) * 2.0f - 1.0f;
        float u2 = __ldg(U + 4) * 2.0f - 1.0f, uv2 = __ldg(U + 5) * 2.0f - 1.0f;

        float4* Q = s_q + tid * 6;
        Q[0] = make_float4(v1x, v1y, v0y - v1y, v0x - v1x);
        Q[1] = make_float4(v2x, v2y, v1y - v2y, v1x - v2x);
        Q[2] = make_float4(v0x, v0y, v2y - v0y, v2x - v0x);
        Q[3] = make_float4(invw, v0z, v1z, v2z);
        Q[4] = make_float4(u0, uv0, u1, uv1);
        Q[5] = make_float4(u2, uv2, 0.0f, 0.0f);

        float xmin = fminf(v0x, fminf(v1x, v2x));
        float xmax = fmaxf(v0x, fmaxf(v1x, v2x));
        float ymin = fminf(v0y, fminf(v1y, v2y));
        float ymax = fmaxf(v0y, fmaxf(v1y, v2y));
        keep = valid && (xmin <= txmax) && (xmax >= txmin) &&
                        (ymin <= tymax) && (ymax >= tymin);
        myzmin = fminf(v0z, fminf(v1z, v2z));
    }

    // zmin warp reduction + compaction ballot
    #pragma unroll
    for (int off = 16; off > 0; off >>= 1)
        myzmin = fminf(myzmin, __shfl_xor_sync(0xffffffffu, myzmin, off));
    unsigned mask = __ballot_sync(0xffffffffu, keep);
    if (lane == 0) { s_wcnt[warp] = __popc(mask); s_zred[warp] = myzmin; }
    __syncthreads();

    float zmin = s_zred[0];
    #pragma unroll
    for (int w = 1; w < 8; w++) zmin = fminf(zmin, s_zred[w]);

    int base = 0, cnt = 0;
    #pragma unroll
    for (int w = 0; w < 8; w++) {
        int c = s_wcnt[w];
        if (w < warp) base += c;
        cnt += c;
    }
    if (keep) s_list[base + __popc(mask & ((1u << lane) - 1u))] = (unsigned short)tid;
    __syncthreads();

    // Pixel coordinates: pts[i][j] = (lin[j], lin[255-i]), lin[k] = -1 + k*2/255
    int j = blockIdx.x * 8 + pcol;
    int i = blockIdx.y * 8 + warp;
    float px = -1.0f + (float)j * d;
    float py =  1.0f - (float)i * d;

    // Each slice scans every 4th surviving triangle (argmax is order-free;
    // within a slice indices ascend so z>=zb keeps the later index on ties).
    float zb = zmin;
    float uu = 0.0f, vv = 0.0f;
    int   bi = -1;

    #pragma unroll 2
    for (int k = slice; k < cnt; k += 4) {
        int tt = s_list[k];
        const float4* Q = s_q + tt * 6;
        float4 q0 = Q[0], q1 = Q[1], q2 = Q[2];

        float pAB = (px - q0.x) * q0.z - (py - q0.y) * q0.w;
        float pCB = (px - q1.x) * q1.z - (py - q1.y) * q1.w;
        float pCA = (px - q2.x) * q2.z - (py - q2.y) * q2.w;

        bool inside = (fmaxf(pAB, 0.0f) * fmaxf(pCB, 0.0f) * fmaxf(pCA, 0.0f)) > 0.0f;
        if (inside) {
            float4 q3 = Q[3];                 // invw, z0, z1, z2
            float w1 = pCB * q3.x;
            float w2 = pCA * q3.x;
            float w3 = 1.0f - w1 - w2;
            float z = w1 * q3.y + w2 * q3.z + w3 * q3.w;
            if (z >= zb) {
                zb = z;
                bi = tt;
                float4 q4 = Q[4];             // u0,v0,u1,v1
                float4 q5 = Q[5];             // u2,v2,-,-
                uu = w1 * q4.x + w2 * q4.z + w3 * q5.x;
                vv = w1 * q4.y + w2 * q4.w + w3 * q5.y;
            }
        }
    }

    // Merge the 4 slices of each pixel: (z, idx) max, ties -> larger idx.
    #pragma unroll
    for (int off = 8; off < 32; off <<= 1) {
        float oz = __shfl_down_sync(0xffffffffu, zb, off);
        int   oi = __shfl_down_sync(0xffffffffu, bi, off);
        float ou = __shfl_down_sync(0xffffffffu, uu, off);
        float ov = __shfl_down_sync(0xffffffffu, vv, off);
        bool take = (oz > zb) || ((oz == zb) && (oi > bi));
        if (take) { zb = oz; bi = oi; uu = ou; vv = ov; }
    }

    if (slice == 0) {
        // Deferred bilinear texture sample for the winning triangle only
        float r = 0.0f, g = 0.0f, b = 0.0f, a = 0.0f;
        if (bi >= 0) {
            a = 1.0f;
            float x = (uu + 1.0f) * 0.5f * 1023.0f;
            float y = (vv + 1.0f) * 0.5f * 1023.0f;
            float x0f = floorf(x);
            float y0f = floorf(y);
            float wx = x - x0f;
            float wy = y - y0f;
            #pragma unroll
            for (int cy = 0; cy < 2; cy++) {
                #pragma unroll
                for (int cx = 0; cx < 2; cx++) {
                    float ix = x0f + (float)cx;
                    float iy = y0f + (float)cy;
                    bool inb = (ix >= 0.0f) && (ix <= 1023.0f) &&
                               (iy >= 0.0f) && (iy <= 1023.0f);
                    if (inb) {
                        int ii = (int)ix;
                        int jj = (int)iy;
                        float wgt = (cx ? wx : 1.0f - wx) * (cy ? wy : 1.0f - wy);
                        int off = jj * 1024 + ii;
                        r += __ldg(uvmap + off) * wgt;
                        g += __ldg(uvmap + 1048576 + off) * wgt;
                        b += __ldg(uvmap + 2097152 + off) * wgt;
                    }
                }
            }
        }

        int pix = i * SZ + j;
        out[pix]              = r;
        out[65536 + pix]      = g;
        out[2 * 65536 + pix]  = b;
        out[3 * 65536 + pix]  = a;
    }
}

extern "C" void kernel_launch(void* const* d_in, const int* in_sizes, int n_in,
                              void* d_out, int out_size) {
    const float* tris  = (const float*)d_in[0];   // (256,3,3)
    const float* uvs   = (const float*)d_in[1];   // (256,3,2)
    const float* uvmap = (const float*)d_in[2];   // (3,1024,1024)
    float* out = (float*)d_out;                   // (4,256,256)

    dim3 block(256);
    dim3 grid(SZ / 8, SZ / 8);
    render_kernel<<<grid, block>>>(tris, uvs, uvmap, out);
}

// round 4
// speedup vs baseline: 1.7851x; 1.0021x over previous
#include <cuda_runtime.h>

#define SZ   256          // image size
#define NT   256          // number of triangles

// Per-triangle record layout (float4 index, 6 per triangle):
//  q0 : pAB edge: ax(=v1x), ay(=v1y), dy(=v0y-v1y), dx(=v0x-v1x)
//  q1 : pCB edge: ax(=v2x), ay(=v2y), dy(=v1y-v2y), dx(=v1x-v2x)
//  q2 : pCA edge: ax(=v0x), ay(=v0y), dy(=v2y-v0y), dx(=v2x-v0x)
//  q3 : invw, z0, z1, z2
//  q4 : u0,v0,u1,v1   (uvs*2-1)
//  q5 : u2,v2,0,0

// Single fused kernel.
// Block: 256 threads = 64 pixels (8x8 tile) x 4 triangle slices.
// Warp layout: lane = slice*8 + pixCol, warp index = pixRow within tile.
// Grid: (32, 32) = 1024 blocks.
//
// Correctness of the slice split: 'inside' implies all barycentric weights > 0,
// so interpolated z is a convex combination of the triangle's vertex z's, hence
// >= global zmin (the zbuf init). The sequential scan therefore reduces to
// argmax over covering triangles (ties -> later index), which is
// order-independent and can be computed in disjoint slices then merged.
//
// Edge culling: each edge function e(p) is affine in p, so over the tile
// rectangle its max is at a corner. If any edge's corner-max <= -1e-5
// (rounding of O(1) fp32 values is < 1e-6), no pixel in the tile can have
// all three edge values strictly positive -> triangle cannot win any pixel.
__global__ __launch_bounds__(256)
void render_kernel(const float* __restrict__ tris,
                   const float* __restrict__ uvs,
                   const float* __restrict__ uvmap,
                   float* __restrict__ out) {
    __shared__ __align__(16) float4 s_q[NT * 6];      // 24 KB
    __shared__ unsigned short s_list[NT];             // float4-offsets (tt*6)
    __shared__ int s_wcnt[8];
    __shared__ float s_zred[8];

    int tid   = threadIdx.x;
    int warp  = tid >> 5;
    int lane  = tid & 31;
    int slice = lane >> 3;        // 0..3
    int pcol  = lane & 7;         // 0..7

    const float d = 2.0f / 255.0f;

    // Tile corner coordinates, computed with the exact per-pixel formula.
    int jx0 = blockIdx.x * 8, jx1 = jx0 + 7;
    int iy0 = blockIdx.y * 8, iy1 = iy0 + 7;
    float cx0 = -1.0f + (float)jx0 * d;   // px at pcol=0
    float cx1 = -1.0f + (float)jx1 * d;   // px at pcol=7
    float cy0 =  1.0f - (float)iy0 * d;   // py at row=0 (max y)
    float cy1 =  1.0f - (float)iy1 * d;   // py at row=7 (min y)

    // ---- Fused prep: thread t builds triangle t's record in shared ----
    bool keep;
    float myzmin;
    {
        const float* T = tris + tid * 9;
        float v0x = __ldg(T + 0), v0y = __ldg(T + 1), v0z = __ldg(T + 2);
        float v1x = __ldg(T + 3), v1y = __ldg(T + 4), v1z = __ldg(T + 5);
        float v2x = __ldg(T + 6), v2y = __ldg(T + 7), v2z = __ldg(T + 8);

        float w = (v1x - v0x) * (v2y - v0y) - (v1y - v0y) * (v2x - v0x);
        bool valid = (w >= 1e-9f);
        float ws = valid ? w : 1.0f;
        float invw = 1.0f / ws;

        const float* U = uvs + tid * 6;
        float u0 = __ldg(U + 0) * 2.0f - 1.0f, uv0 = __ldg(U + 1) * 2.0f - 1.0f;
        float u1 = __ldg(U + 2) * 2.0f - 1.0f, uv1 = __ldg(U + 3) * 2.0f - 1.0f;
        float u2 = __ldg(U + 4) * 2.0f - 1.0f, uv2 = __ldg(U + 5) * 2.0f - 1.0f;

        float4* Q = s_q + tid * 6;
        Q[0] = make_float4(v1x, v1y, v0y - v1y, v0x - v1x);
        Q[1] = make_float4(v2x, v2y, v1y - v2y, v1x - v2x);
        Q[2] = make_float4(v0x, v0y, v2y - v0y, v2x - v0x);
        Q[3] = make_float4(invw, v0z, v1z, v2z);
        Q[4] = make_float4(u0, uv0, u1, uv1);
        Q[5] = make_float4(u2, uv2, 0.0f, 0.0f);

        // Edge corner-max cull: e = (cx-ax)*dy - (cy-ay)*dx is separable,
        // max = max_x[(cx-ax)*dy] + max_y[-(cy-ay)*dx].
        #define EDGE_MAX(ax, ay, dy, dx) \
            (fmaxf((cx0 - (ax)) * (dy), (cx1 - (ax)) * (dy)) + \
             fmaxf(-((cy0 - (ay)) * (dx)), -((cy1 - (ay)) * (dx))))
        float mAB = EDGE_MAX(v1x, v1y, v0y - v1y, v0x - v1x);
        float mCB = EDGE_MAX(v2x, v2y, v1y - v2y, v1x - v2x);
        float mCA = EDGE_MAX(v0x, v0y, v2y - v0y, v2x - v0x);
        #undef EDGE_MAX

        keep = valid && (mAB > -1e-5f) && (mCB > -1e-5f) && (mCA > -1e-5f);
        myzmin = fminf(v0z, fminf(v1z, v2z));
    }

    // zmin warp reduction + compaction ballot
    #pragma unroll
    for (int off = 16; off > 0; off >>= 1)
        myzmin = fminf(myzmin, __shfl_xor_sync(0xffffffffu, myzmin, off));
    unsigned mask = __ballot_sync(0xffffffffu, keep);
    if (lane == 0) { s_wcnt[warp] = __popc(mask); s_zred[warp] = myzmin; }
    __syncthreads();

    float zmin = s_zred[0];
    #pragma unroll
    for (int w = 1; w < 8; w++) zmin = fminf(zmin, s_zred[w]);

    int base = 0, cnt = 0;
    #pragma unroll
    for (int w = 0; w < 8; w++) {
        int c = s_wcnt[w];
        if (w < warp) base += c;
        cnt += c;
    }
    if (keep)
        s_list[base + __popc(mask & ((1u << lane) - 1u))] =
            (unsigned short)(tid * 6);   // store float4 offset; monotone in tid
    __syncthreads();

    // Pixel coordinates: pts[i][j] = (lin[j], lin[255-i]), lin[k] = -1 + k*2/255
    int j = jx0 + pcol;
    int i = iy0 + warp;
    float px = -1.0f + (float)j * d;
    float py =  1.0f - (float)i * d;

    // Each slice scans every 4th surviving triangle (argmax is order-free;
    // within a slice offsets ascend so z>=zb keeps the later index on ties).
    float zb = zmin;
    float uu = 0.0f, vv = 0.0f;
    int   bi = -1;                 // winning float4-offset (monotone in index)

    // Software-pipelined loop: prefetch next list entry + first record quads.
    int k = slice;
    int off_c = 0;
    float4 q0c, q1c, q2c;
    if (k < cnt) {
        off_c = s_list[k];
        const float4* Q = s_q + off_c;
        q0c = Q[0]; q1c = Q[1]; q2c = Q[2];
    }
    for (; k < cnt; ) {
        int kn = k + 4;
        int off_n = 0;
        float4 q0n, q1n, q2n;
        if (kn < cnt) {
            off_n = s_list[kn];
            const float4* Qn = s_q + off_n;
            q0n = Qn[0]; q1n = Qn[1]; q2n = Qn[2];
        }

        float pAB = (px - q0c.x) * q0c.z - (py - q0c.y) * q0c.w;
        float pCB = (px - q1c.x) * q1c.z - (py - q1c.y) * q1c.w;
        float pCA = (px - q2c.x) * q2c.z - (py - q2c.y) * q2c.w;

        bool inside = (fmaxf(pAB, 0.0f) * fmaxf(pCB, 0.0f) * fmaxf(pCA, 0.0f)) > 0.0f;
        if (inside) {
            float4 q3 = s_q[off_c + 3];       // invw, z0, z1, z2
            float w1 = pCB * q3.x;
            float w2 = pCA * q3.x;
            float w3 = 1.0f - w1 - w2;
            float z = w1 * q3.y + w2 * q3.z + w3 * q3.w;
            if (z >= zb) {
                zb = z;
                bi = off_c;
                float4 q4 = s_q[off_c + 4];   // u0,v0,u1,v1
                float4 q5 = s_q[off_c + 5];   // u2,v2,-,-
                uu = w1 * q4.x + w2 * q4.z + w3 * q5.x;
                vv = w1 * q4.y + w2 * q4.w + w3 * q5.y;
            }
        }

        k = kn;
        off_c = off_n;
        q0c = q0n; q1c = q1n; q2c = q2n;
    }

    // Merge the 4 slices of each pixel: (z, off) max, ties -> larger off.
    #pragma unroll
    for (int off = 8; off < 32; off <<= 1) {
        float oz = __shfl_down_sync(0xffffffffu, zb, off);
        int   oi = __shfl_down_sync(0xffffffffu, bi, off);
        float ou = __shfl_down_sync(0xffffffffu, uu, off);
        float ov = __shfl_down_sync(0xffffffffu, vv, off);
        bool take = (oz > zb) || ((oz == zb) && (oi > bi));
        if (take) { zb = oz; bi = oi; uu = ou; vv = ov; }
    }

    if (slice == 0) {
        // Deferred bilinear texture sample for the winning triangle only
        float r = 0.0f, g = 0.0f, b = 0.0f, a = 0.0f;
        if (bi >= 0) {
            a = 1.0f;
            float x = (uu + 1.0f) * 0.5f * 1023.0f;
            float y = (vv + 1.0f) * 0.5f * 1023.0f;
            float x0f = floorf(x);
            float y0f = floorf(y);
            float wx = x - x0f;
            float wy = y - y0f;
            #pragma unroll
            for (int cy = 0; cy < 2; cy++) {
                #pragma unroll
                for (int cx = 0; cx < 2; cx++) {
                    float ix = x0f + (float)cx;
                    float iy = y0f + (float)cy;
                    bool inb = (ix >= 0.0f) && (ix <= 1023.0f) &&
                               (iy >= 0.0f) && (iy <= 1023.0f);
                    if (inb) {
                        int ii = (int)ix;
                        int jj = (int)iy;
                        float wgt = (cx ? wx : 1.0f - wx) * (cy ? wy : 1.0f - wy);
                        int toff = jj * 1024 + ii;
                        r += __ldg(uvmap + toff) * wgt;
                        g += __ldg(uvmap + 1048576 + toff) * wgt;
                        b += __ldg(uvmap + 2097152 + toff) * wgt;
                    }
                }
            }
        }

        int pix = i * SZ + j;
        out[pix]              = r;
        out[65536 + pix]      = g;
        out[2 * 65536 + pix]  = b;
        out[3 * 65536 + pix]  = a;
    }
}

extern "C" void kernel_launch(void* const* d_in, const int* in_sizes, int n_in,
                              void* d_out, int out_size) {
    const float* tris  = (const float*)d_in[0];   // (256,3,3)
    const float* uvs   = (const float*)d_in[1];   // (256,3,2)
    const float* uvmap = (const float*)d_in[2];   // (3,1024,1024)
    float* out = (float*)d_out;                   // (4,256,256)

    dim3 block(256);
    dim3 grid(SZ / 8, SZ / 8);
    render_kernel<<<grid, block>>>(tris, uvs, uvmap, out);
}

// round 5
// speedup vs baseline: 2.0614x; 1.1548x over previous
#include <cuda_runtime.h>

#define SZ   256          // image size
#define NT   256          // number of triangles

// Per-triangle record layout (float4 index, 4 per triangle, 16 KB total):
//  q0 : pAB edge: ax(=v1x), ay(=v1y), dy(=v0y-v1y), dx(=v0x-v1x)
//  q1 : pCB edge: ax(=v2x), ay(=v2y), dy(=v1y-v2y), dx(=v1x-v2x)
//  q2 : pCA edge: ax(=v0x), ay(=v0y), dy(=v2y-v0y), dx(=v2x-v0x)
//  q3 : invw, z0, z1, z2
// UV data is NOT staged: the winning triangle's uvs are fetched from global
// in the tail (once per pixel) and transformed there — identical arithmetic.

// Single fused kernel.
// Block: 256 threads = 64 pixels (8x8 tile) x 4 triangle slices.
// Warp layout: lane = slice*8 + pixCol, warp index = pixRow within tile.
// Grid: (32, 32) = 1024 blocks.
//
// Correctness of the slice split: 'inside' implies all barycentric weights > 0,
// so interpolated z is a convex combination of the triangle's vertex z's, hence
// >= global zmin (the zbuf init). The sequential scan therefore reduces to
// argmax over covering triangles (ties -> later index), which is
// order-independent and can be computed in disjoint slices then merged.
//
// Edge culling: each edge function e(p) is affine in p, so over the tile
// rectangle its max is at a corner. If any edge's corner-max <= -1e-5
// (rounding of O(1) fp32 values is < 1e-6), no pixel in the tile can have
// all three edge values strictly positive -> triangle cannot win any pixel.
//
// NOTE: the inside-test arithmetic form (px-ax)*dy-(py-ay)*dx must match the
// reference exactly — refactoring it flips boundary pixels and fails 1e-3.
__global__ __launch_bounds__(256, 7)
void render_kernel(const float* __restrict__ tris,
                   const float* __restrict__ uvs,
                   const float* __restrict__ uvmap,
                   float* __restrict__ out) {
    __shared__ __align__(16) float4 s_q[NT * 4];      // 16 KB
    __shared__ unsigned short s_list[NT];             // float4-offsets (tt*4)
    __shared__ int s_wcnt[8];
    __shared__ float s_zred[8];

    int tid   = threadIdx.x;
    int warp  = tid >> 5;
    int lane  = tid & 31;
    int slice = lane >> 3;        // 0..3
    int pcol  = lane & 7;         // 0..7

    const float d = 2.0f / 255.0f;

    // Tile corner coordinates, computed with the exact per-pixel formula.
    int jx0 = blockIdx.x * 8, jx1 = jx0 + 7;
    int iy0 = blockIdx.y * 8, iy1 = iy0 + 7;
    float cx0 = -1.0f + (float)jx0 * d;   // px at pcol=0
    float cx1 = -1.0f + (float)jx1 * d;   // px at pcol=7
    float cy0 =  1.0f - (float)iy0 * d;   // py at row=0 (max y)
    float cy1 =  1.0f - (float)iy1 * d;   // py at row=7 (min y)

    // ---- Fused prep: thread t builds triangle t's record in shared ----
    bool keep;
    float myzmin;
    {
        const float* T = tris + tid * 9;
        float v0x = __ldg(T + 0), v0y = __ldg(T + 1), v0z = __ldg(T + 2);
        float v1x = __ldg(T + 3), v1y = __ldg(T + 4), v1z = __ldg(T + 5);
        float v2x = __ldg(T + 6), v2y = __ldg(T + 7), v2z = __ldg(T + 8);

        float w = (v1x - v0x) * (v2y - v0y) - (v1y - v0y) * (v2x - v0x);
        bool valid = (w >= 1e-9f);
        float ws = valid ? w : 1.0f;
        float invw = 1.0f / ws;

        float4* Q = s_q + tid * 4;
        Q[0] = make_float4(v1x, v1y, v0y - v1y, v0x - v1x);
        Q[1] = make_float4(v2x, v2y, v1y - v2y, v1x - v2x);
        Q[2] = make_float4(v0x, v0y, v2y - v0y, v2x - v0x);
        Q[3] = make_float4(invw, v0z, v1z, v2z);

        // Edge corner-max cull: e = (cx-ax)*dy - (cy-ay)*dx is separable,
        // max = max_x[(cx-ax)*dy] + max_y[-(cy-ay)*dx].
        #define EDGE_MAX(ax, ay, dy, dx) \
            (fmaxf((cx0 - (ax)) * (dy), (cx1 - (ax)) * (dy)) + \
             fmaxf(-((cy0 - (ay)) * (dx)), -((cy1 - (ay)) * (dx))))
        float mAB = EDGE_MAX(v1x, v1y, v0y - v1y, v0x - v1x);
        float mCB = EDGE_MAX(v2x, v2y, v1y - v2y, v1x - v2x);
        float mCA = EDGE_MAX(v0x, v0y, v2y - v0y, v2x - v0x);
        #undef EDGE_MAX

        keep = valid && (mAB > -1e-5f) && (mCB > -1e-5f) && (mCA > -1e-5f);
        myzmin = fminf(v0z, fminf(v1z, v2z));
    }

    // zmin warp reduction + compaction ballot
    #pragma unroll
    for (int off = 16; off > 0; off >>= 1)
        myzmin = fminf(myzmin, __shfl_xor_sync(0xffffffffu, myzmin, off));
    unsigned mask = __ballot_sync(0xffffffffu, keep);
    if (lane == 0) { s_wcnt[warp] = __popc(mask); s_zred[warp] = myzmin; }
    __syncthreads();

    float zmin = s_zred[0];
    #pragma unroll
    for (int w = 1; w < 8; w++) zmin = fminf(zmin, s_zred[w]);

    int base = 0, cnt = 0;
    #pragma unroll
    for (int w = 0; w < 8; w++) {
        int c = s_wcnt[w];
        if (w < warp) base += c;
        cnt += c;
    }
    if (keep)
        s_list[base + __popc(mask & ((1u << lane) - 1u))] =
            (unsigned short)(tid * 4);   // store float4 offset; monotone in tid
    __syncthreads();

    // Pixel coordinates: pts[i][j] = (lin[j], lin[255-i]), lin[k] = -1 + k*2/255
    int j = jx0 + pcol;
    int i = iy0 + warp;
    float px = -1.0f + (float)j * d;
    float py =  1.0f - (float)i * d;

    // Each slice scans every 4th surviving triangle (argmax is order-free;
    // within a slice offsets ascend so z>=zb keeps the later index on ties).
    float zb = zmin;
    float w1s = 0.0f, w2s = 0.0f;
    int   bi = -1;                 // winning float4-offset (monotone in index)

    // Software-pipelined loop: prefetch next list entry + record quads.
    int k = slice;
    int off_c = 0;
    float4 q0c, q1c, q2c;
    if (k < cnt) {
        off_c = s_list[k];
        const float4* Q = s_q + off_c;
        q0c = Q[0]; q1c = Q[1]; q2c = Q[2];
    }
    for (; k < cnt; ) {
        int kn = k + 4;
        int off_n = 0;
        float4 q0n, q1n, q2n;
        if (kn < cnt) {
            off_n = s_list[kn];
            const float4* Qn = s_q + off_n;
            q0n = Qn[0]; q1n = Qn[1]; q2n = Qn[2];
        }

        float pAB = (px - q0c.x) * q0c.z - (py - q0c.y) * q0c.w;
        float pCB = (px - q1c.x) * q1c.z - (py - q1c.y) * q1c.w;
        float pCA = (px - q2c.x) * q2c.z - (py - q2c.y) * q2c.w;

        bool inside = (fmaxf(pAB, 0.0f) * fmaxf(pCB, 0.0f) * fmaxf(pCA, 0.0f)) > 0.0f;
        if (inside) {
            float4 q3 = s_q[off_c + 3];       // invw, z0, z1, z2
            float w1 = pCB * q3.x;
            float w2 = pCA * q3.x;
            float w3 = 1.0f - w1 - w2;
            float z = w1 * q3.y + w2 * q3.z + w3 * q3.w;
            if (z >= zb) {
                zb = z;
                bi = off_c;
                w1s = w1;
                w2s = w2;
            }
        }

        k = kn;
        off_c = off_n;
        q0c = q0n; q1c = q1n; q2c = q2n;
    }

    // Merge the 4 slices of each pixel: (z, off) max, ties -> larger off.
    #pragma unroll
    for (int off = 8; off < 32; off <<= 1) {
        float oz = __shfl_down_sync(0xffffffffu, zb, off);
        int   oi = __shfl_down_sync(0xffffffffu, bi, off);
        float o1 = __shfl_down_sync(0xffffffffu, w1s, off);
        float o2 = __shfl_down_sync(0xffffffffu, w2s, off);
        bool take = (oz > zb) || ((oz == zb) && (oi > bi));
        if (take) { zb = oz; bi = oi; w1s = o1; w2s = o2; }
    }

    if (slice == 0) {
        // Deferred UV interpolation + bilinear texture sample (winner only)
        float r = 0.0f, g = 0.0f, b = 0.0f, a = 0.0f;
        if (bi >= 0) {
            a = 1.0f;
            const float* U = uvs + (bi >> 2) * 6;   // bi = tt*4
            float u0 = __ldg(U + 0) * 2.0f - 1.0f, v0 = __ldg(U + 1) * 2.0f - 1.0f;
            float u1 = __ldg(U + 2) * 2.0f - 1.0f, v1 = __ldg(U + 3) * 2.0f - 1.0f;
            float u2 = __ldg(U + 4) * 2.0f - 1.0f, v2 = __ldg(U + 5) * 2.0f - 1.0f;
            float w3 = 1.0f - w1s - w2s;
            float uu = w1s * u0 + w2s * u1 + w3 * u2;
            float vv = w1s * v0 + w2s * v1 + w3 * v2;

            float x = (uu + 1.0f) * 0.5f * 1023.0f;
            float y = (vv + 1.0f) * 0.5f * 1023.0f;
            float x0f = floorf(x);
            float y0f = floorf(y);
            float wx = x - x0f;
            float wy = y - y0f;
            #pragma unroll
            for (int cy = 0; cy < 2; cy++) {
                #pragma unroll
                for (int cx = 0; cx < 2; cx++) {
                    float ix = x0f + (float)cx;
                    float iy = y0f + (float)cy;
                    bool inb = (ix >= 0.0f) && (ix <= 1023.0f) &&
                               (iy >= 0.0f) && (iy <= 1023.0f);
                    if (inb) {
                        int ii = (int)ix;
                        int jj = (int)iy;
                        float wgt = (cx ? wx : 1.0f - wx) * (cy ? wy : 1.0f - wy);
                        int toff = jj * 1024 + ii;
                        r += __ldg(uvmap + toff) * wgt;
                        g += __ldg(uvmap + 1048576 + toff) * wgt;
                        b += __ldg(uvmap + 2097152 + toff) * wgt;
                    }
                }
            }
        }

        int pix = i * SZ + j;
        out[pix]              = r;
        out[65536 + pix]      = g;
        out[2 * 65536 + pix]  = b;
        out[3 * 65536 + pix]  = a;
    }
}

extern "C" void kernel_launch(void* const* d_in, const int* in_sizes, int n_in,
                              void* d_out, int out_size) {
    const float* tris  = (const float*)d_in[0];   // (256,3,3)
    const float* uvs   = (const float*)d_in[1];   // (256,3,2)
    const float* uvmap = (const float*)d_in[2];   // (3,1024,1024)
    float* out = (float*)d_out;                   // (4,256,256)

    dim3 block(256);
    dim3 grid(SZ / 8, SZ / 8);
    render_kernel<<<grid, block>>>(tris, uvs, uvmap, out);
}

// round 6
// speedup vs baseline: 2.1294x; 1.0330x over previous
#include <cuda_runtime.h>

#define SZ   256          // image size
#define NT   256          // number of triangles

// Per-triangle record layout (float4 index, 4 per triangle, 16 KB total):
//  q0 : pAB edge: ax(=v1x), ay(=v1y), dy(=v0y-v1y), dx(=v0x-v1x)
//  q1 : pCB edge: ax(=v2x), ay(=v2y), dy(=v1y-v2y), dx(=v1x-v2x)
//  q2 : pCA edge: ax(=v0x), ay(=v0y), dy(=v2y-v0y), dx(=v2x-v0x)
//  q3 : invw, z0, z1, z2
// UV data is NOT staged: the winning triangle's uvs are fetched from global
// in the tail (once per pixel) and transformed there — identical arithmetic.

// Single fused kernel.
// Block: 256 threads = 64 pixels (8x8 tile) x 4 triangle slices.
// Warp layout: lane = slice*8 + pixCol, warp index = pixRow within tile.
// Grid: (32, 32) = 1024 blocks -> single wave at 7 CTAs/SM.
//
// The z-buffer scan reduces to an argmax over covering triangles with ties
// broken by larger triangle index ('inside' => all barycentric weights > 0 =>
// z is a convex combination of vertex z's => z >= global zmin, so the zbuf
// init never matters for covered pixels). Argmax is order-independent:
// the candidate list needs NO ordering (tie-break uses the stored offset),
// and slices can be merged by shuffle reduction.
//
// Edge culling: each edge function e(p) is affine in p, so over the tile
// rectangle its max is at a corner. If any edge's corner-max <= -1e-5
// (rounding of O(1) fp32 values is < 1e-6), no pixel in the tile can have
// all three edge values strictly positive -> triangle cannot win any pixel.
//
// NOTE: the inside-test arithmetic form (px-ax)*dy-(py-ay)*dx must match the
// reference exactly — refactoring it flips boundary pixels and fails 1e-3.
__global__ __launch_bounds__(256, 7)
void render_kernel(const float* __restrict__ tris,
                   const float* __restrict__ uvs,
                   const float* __restrict__ uvmap,
                   float* __restrict__ out) {
    __shared__ __align__(16) float4 s_q[NT * 4];      // 16 KB
    __shared__ unsigned short s_list[NT];             // float4-offsets (tt*4), UNORDERED
    __shared__ int s_cnt;

    int tid   = threadIdx.x;
    int lane  = tid & 31;
    int warp  = tid >> 5;
    int slice = lane >> 3;        // 0..3
    int pcol  = lane & 7;         // 0..7

    const float d = 2.0f / 255.0f;

    if (tid == 0) s_cnt = 0;

    // Tile corner coordinates, computed with the exact per-pixel formula.
    int jx0 = blockIdx.x * 8, jx1 = jx0 + 7;
    int iy0 = blockIdx.y * 8, iy1 = iy0 + 7;
    float cx0 = -1.0f + (float)jx0 * d;   // px at pcol=0
    float cx1 = -1.0f + (float)jx1 * d;   // px at pcol=7
    float cy0 =  1.0f - (float)iy0 * d;   // py at row=0 (max y)
    float cy1 =  1.0f - (float)iy1 * d;   // py at row=7 (min y)

    // ---- Fused prep: thread t builds triangle t's record in shared ----
    bool keep;
    {
        const float* T = tris + tid * 9;
        float v0x = __ldg(T + 0), v0y = __ldg(T + 1), v0z = __ldg(T + 2);
        float v1x = __ldg(T + 3), v1y = __ldg(T + 4), v1z = __ldg(T + 5);
        float v2x = __ldg(T + 6), v2y = __ldg(T + 7), v2z = __ldg(T + 8);

        float w = (v1x - v0x) * (v2y - v0y) - (v1y - v0y) * (v2x - v0x);
        bool valid = (w >= 1e-9f);
        float ws = valid ? w : 1.0f;
        float invw = 1.0f / ws;

        float4* Q = s_q + tid * 4;
        Q[0] = make_float4(v1x, v1y, v0y - v1y, v0x - v1x);
        Q[1] = make_float4(v2x, v2y, v1y - v2y, v1x - v2x);
        Q[2] = make_float4(v0x, v0y, v2y - v0y, v2x - v0x);
        Q[3] = make_float4(invw, v0z, v1z, v2z);

        // Edge corner-max cull: e = (cx-ax)*dy - (cy-ay)*dx is separable,
        // max = max_x[(cx-ax)*dy] + max_y[-(cy-ay)*dx].
        #define EDGE_MAX(ax, ay, dy, dx) \
            (fmaxf((cx0 - (ax)) * (dy), (cx1 - (ax)) * (dy)) + \
             fmaxf(-((cy0 - (ay)) * (dx)), -((cy1 - (ay)) * (dx))))
        float mAB = EDGE_MAX(v1x, v1y, v0y - v1y, v0x - v1x);
        float mCB = EDGE_MAX(v2x, v2y, v1y - v2y, v1x - v2x);
        float mCA = EDGE_MAX(v0x, v0y, v2y - v0y, v2x - v0x);
        #undef EDGE_MAX

        keep = valid && (mAB > -1e-5f) && (mCB > -1e-5f) && (mCA > -1e-5f);
    }

    // Unordered compaction: ballot + one shared atomic per warp.
    // (s_cnt=0 must be visible before the atomics; prep work hides the sync.)
    __syncthreads();
    unsigned mask = __ballot_sync(0xffffffffu, keep);
    int base = 0;
    if (lane == 0 && mask) base = atomicAdd(&s_cnt, __popc(mask));
    base = __shfl_sync(0xffffffffu, base, 0);
    if (keep)
        s_list[base + __popc(mask & ((1u << lane) - 1u))] =
            (unsigned short)(tid * 4);   // float4 offset; monotone in tid VALUE
    __syncthreads();
    int cnt = s_cnt;

    // Pixel coordinates: pts[i][j] = (lin[j], lin[255-i]), lin[k] = -1 + k*2/255
    int j = jx0 + pcol;
    int i = iy0 + warp;
    float px = -1.0f + (float)j * d;
    float py =  1.0f - (float)i * d;

    // Each slice scans every 4th surviving triangle. Branch-free body:
    // z computed unconditionally (all records finite), update via selects.
    // Tie-break (z equal) -> larger stored offset == larger triangle index,
    // exactly matching the reference's last-writer-wins.
    float zb  = -3.402823466e+38f;
    float w1s = 0.0f, w2s = 0.0f;
    int   bi  = -1;

    for (int k = slice; k < cnt; k += 4) {
        int off = s_list[k];
        float4 q0 = s_q[off], q1 = s_q[off + 1], q2 = s_q[off + 2], q3 = s_q[off + 3];

        float pAB = (px - q0.x) * q0.z - (py - q0.y) * q0.w;
        float pCB = (px - q1.x) * q1.z - (py - q1.y) * q1.w;
        float pCA = (px - q2.x) * q2.z - (py - q2.y) * q2.w;

        float prod = fmaxf(pAB, 0.0f) * fmaxf(pCB, 0.0f) * fmaxf(pCA, 0.0f);

        float w1 = pCB * q3.x;
        float w2 = pCA * q3.x;
        float w3 = 1.0f - w1 - w2;
        float z  = w1 * q3.y + w2 * q3.z + w3 * q3.w;

        bool take = (prod > 0.0f) &&
                    ((z > zb) || ((z == zb) && (off > bi)));
        zb  = take ? z   : zb;
        bi  = take ? off : bi;
        w1s = take ? w1  : w1s;
        w2s = take ? w2  : w2s;
    }

    // Merge the 4 slices of each pixel: (z, off) max, ties -> larger off.
    #pragma unroll
    for (int off = 8; off < 32; off <<= 1) {
        float oz = __shfl_down_sync(0xffffffffu, zb, off);
        int   oi = __shfl_down_sync(0xffffffffu, bi, off);
        float o1 = __shfl_down_sync(0xffffffffu, w1s, off);
        float o2 = __shfl_down_sync(0xffffffffu, w2s, off);
        bool take = (oz > zb) || ((oz == zb) && (oi > bi));
        if (take) { zb = oz; bi = oi; w1s = o1; w2s = o2; }
    }

    if (slice == 0) {
        // Deferred UV interpolation + bilinear texture sample (winner only)
        float r = 0.0f, g = 0.0f, b = 0.0f, a = 0.0f;
        if (bi >= 0) {
            a = 1.0f;
            const float* U = uvs + (bi >> 2) * 6;   // bi = tt*4
            float u0 = __ldg(U + 0) * 2.0f - 1.0f, v0 = __ldg(U + 1) * 2.0f - 1.0f;
            float u1 = __ldg(U + 2) * 2.0f - 1.0f, v1 = __ldg(U + 3) * 2.0f - 1.0f;
            float u2 = __ldg(U + 4) * 2.0f - 1.0f, v2 = __ldg(U + 5) * 2.0f - 1.0f;
            float w3 = 1.0f - w1s - w2s;
            float uu = w1s * u0 + w2s * u1 + w3 * u2;
            float vv = w1s * v0 + w2s * v1 + w3 * v2;

            float x = (uu + 1.0f) * 0.5f * 1023.0f;
            float y = (vv + 1.0f) * 0.5f * 1023.0f;
            float x0f = floorf(x);
            float y0f = floorf(y);
            float wx = x - x0f;
            float wy = y - y0f;
            #pragma unroll
            for (int cy = 0; cy < 2; cy++) {
                #pragma unroll
                for (int cx = 0; cx < 2; cx++) {
                    float ix = x0f + (float)cx;
                    float iy = y0f + (float)cy;
                    bool inb = (ix >= 0.0f) && (ix <= 1023.0f) &&
                               (iy >= 0.0f) && (iy <= 1023.0f);
                    if (inb) {
                        int ii = (int)ix;
                        int jj = (int)iy;
                        float wgt = (cx ? wx : 1.0f - wx) * (cy ? wy : 1.0f - wy);
                        int toff = jj * 1024 + ii;
                        r += __ldg(uvmap + toff) * wgt;
                        g += __ldg(uvmap + 1048576 + toff) * wgt;
                        b += __ldg(uvmap + 2097152 + toff) * wgt;
                    }
                }
            }
        }

        int pix = i * SZ + j;
        out[pix]              = r;
        out[65536 + pix]      = g;
        out[2 * 65536 + pix]  = b;
        out[3 * 65536 + pix]  = a;
    }
}

extern "C" void kernel_launch(void* const* d_in, const int* in_sizes, int n_in,
                              void* d_out, int out_size) {
    const float* tris  = (const float*)d_in[0];   // (256,3,3)
    const float* uvs   = (const float*)d_in[1];   // (256,3,2)
    const float* uvmap = (const float*)d_in[2];   // (3,1024,1024)
    float* out = (float*)d_out;                   // (4,256,256)

    dim3 block(256);
    dim3 grid(SZ / 8, SZ / 8);
    render_kernel<<<grid, block>>>(tris, uvs, uvmap, out);
}

// round 7
// speedup vs baseline: 2.4532x; 1.1520x over previous
#include <cuda_runtime.h>

#define SZ   256          // image size
#define NT   256          // number of triangles
#define QSTRIDE 5         // float4 per triangle record (80B: kills bank conflicts)

// Per-triangle record layout (float4 index, stride 5, 80 B):
//  q0 : pAB edge: ax(=v1x), ay(=v1y), dy(=v0y-v1y), dx(=v0x-v1x)
//  q1 : pCB edge: ax(=v2x), ay(=v2y), dy(=v1y-v2y), dx(=v1x-v2x)
//  q2 : pCA edge: ax(=v0x), ay(=v0y), dy(=v2y-v0y), dx(=v2x-v0x)
//  q3 : invw, z0, z1, z2
//  q4 : pad (written zero)
// Slot NT is an all-zero "null" record: prod==0 -> never taken. Used to pad
// the candidate list so the x2-unrolled loop needs no tail guard.
//
// UV data is NOT staged: the winning triangle's uvs are fetched from global
// in the tail (once per pixel) and transformed there — identical arithmetic.
//
// Block: 256 threads = 64 pixels (8x8 tile) x 4 triangle slices.
// Warp layout: lane = slice*8 + pixCol, warp index = pixRow within tile.
// Grid: (32, 32) = 1024 blocks -> single wave.
//
// The z-buffer scan reduces to an argmax over covering triangles with ties
// broken by larger triangle index ('inside' => all barycentric weights > 0 =>
// z is a convex combination of vertex z's => z >= global zmin, so the zbuf
// init never matters for covered pixels). Argmax is order-independent:
// the candidate list needs NO ordering (tie-break uses the stored offset,
// monotone in triangle index), and slices merge by shuffle reduction.
//
// Edge culling: each edge function e(p) is affine in p, so over the tile
// rectangle its max is at a corner. If any edge's corner-max <= -1e-5
// (rounding of O(1) fp32 values is < 1e-6), no pixel in the tile can have
// all three edge values strictly positive -> triangle cannot win any pixel.
//
// NOTE: the inside-test arithmetic form (px-ax)*dy-(py-ay)*dx must match the
// reference exactly — refactoring it flips boundary pixels and fails 1e-3.
__global__ __launch_bounds__(256, 6)
void render_kernel(const float* __restrict__ tris,
                   const float* __restrict__ uvs,
                   const float* __restrict__ uvmap,
                   float* __restrict__ out) {
    __shared__ __align__(16) float4 s_q[(NT + 1) * QSTRIDE];  // ~20.6 KB
    __shared__ unsigned short s_list[NT + 8];                 // quad offsets (tt*5)
    __shared__ int s_cnt;

    int tid   = threadIdx.x;
    int lane  = tid & 31;
    int warp  = tid >> 5;
    int slice = lane >> 3;        // 0..3
    int pcol  = lane & 7;         // 0..7

    const float d = 2.0f / 255.0f;

    if (tid == 0) s_cnt = 0;
    if (tid < QSTRIDE)            // null record (never wins: prod == 0)
        s_q[NT * QSTRIDE + tid] = make_float4(0.0f, 0.0f, 0.0f, 0.0f);

    // Tile corner coordinates, computed with the exact per-pixel formula.
    int jx0 = blockIdx.x * 8, jx1 = jx0 + 7;
    int iy0 = blockIdx.y * 8, iy1 = iy0 + 7;
    float cx0 = -1.0f + (float)jx0 * d;   // px at pcol=0
    float cx1 = -1.0f + (float)jx1 * d;   // px at pcol=7
    float cy0 =  1.0f - (float)iy0 * d;   // py at row=0 (max y)
    float cy1 =  1.0f - (float)iy1 * d;   // py at row=7 (min y)

    // ---- Fused prep: thread t builds triangle t's record in shared ----
    bool keep;
    {
        const float* T = tris + tid * 9;
        float v0x = __ldg(T + 0), v0y = __ldg(T + 1), v0z = __ldg(T + 2);
        float v1x = __ldg(T + 3), v1y = __ldg(T + 4), v1z = __ldg(T + 5);
        float v2x = __ldg(T + 6), v2y = __ldg(T + 7), v2z = __ldg(T + 8);

        float w = (v1x - v0x) * (v2y - v0y) - (v1y - v0y) * (v2x - v0x);
        bool valid = (w >= 1e-9f);
        float ws = valid ? w : 1.0f;
        float invw = 1.0f / ws;

        float4* Q = s_q + tid * QSTRIDE;
        Q[0] = make_float4(v1x, v1y, v0y - v1y, v0x - v1x);
        Q[1] = make_float4(v2x, v2y, v1y - v2y, v1x - v2x);
        Q[2] = make_float4(v0x, v0y, v2y - v0y, v2x - v0x);
        Q[3] = make_float4(invw, v0z, v1z, v2z);
        Q[4] = make_float4(0.0f, 0.0f, 0.0f, 0.0f);

        // Edge corner-max cull: e = (cx-ax)*dy - (cy-ay)*dx is separable,
        // max = max_x[(cx-ax)*dy] + max_y[-(cy-ay)*dx].
        #define EDGE_MAX(ax, ay, dy, dx) \
            (fmaxf((cx0 - (ax)) * (dy), (cx1 - (ax)) * (dy)) + \
             fmaxf(-((cy0 - (ay)) * (dx)), -((cy1 - (ay)) * (dx))))
        float mAB = EDGE_MAX(v1x, v1y, v0y - v1y, v0x - v1x);
        float mCB = EDGE_MAX(v2x, v2y, v1y - v2y, v1x - v2x);
        float mCA = EDGE_MAX(v0x, v0y, v2y - v0y, v2x - v0x);
        #undef EDGE_MAX

        keep = valid && (mAB > -1e-5f) && (mCB > -1e-5f) && (mCA > -1e-5f);
    }

    // Unordered compaction: ballot + one shared atomic per warp.
    __syncthreads();
    unsigned mask = __ballot_sync(0xffffffffu, keep);
    int base = 0;
    if (lane == 0 && mask) base = atomicAdd(&s_cnt, __popc(mask));
    base = __shfl_sync(0xffffffffu, base, 0);
    if (keep)
        s_list[base + __popc(mask & ((1u << lane) - 1u))] =
            (unsigned short)(tid * QSTRIDE);   // quad offset; monotone in tid
    __syncthreads();
    int cnt = s_cnt;
    if (tid < 8) s_list[cnt + tid] = (unsigned short)(NT * QSTRIDE); // null pad
    __syncthreads();

    // Pixel coordinates: pts[i][j] = (lin[j], lin[255-i]), lin[k] = -1 + k*2/255
    int j = jx0 + pcol;
    int i = iy0 + warp;
    float px = -1.0f + (float)j * d;
    float py =  1.0f - (float)i * d;

    // Each slice scans every 4th surviving triangle, two per loop iteration
    // (second may be the null record -> never taken). Branch-free updates;
    // tie-break (z equal) -> larger stored offset == larger triangle index.
    float zb  = -3.402823466e+38f;
    float w1s = 0.0f, w2s = 0.0f;
    int   bi  = -1;

    #define EVAL(OFF)                                                        \
    {                                                                        \
        int off = (OFF);                                                     \
        float4 q0 = s_q[off], q1 = s_q[off + 1],                             \
               q2 = s_q[off + 2], q3 = s_q[off + 3];                         \
        float pAB = (px - q0.x) * q0.z - (py - q0.y) * q0.w;                 \
        float pCB = (px - q1.x) * q1.z - (py - q1.y) * q1.w;                 \
        float pCA = (px - q2.x) * q2.z - (py - q2.y) * q2.w;                 \
        float prod = fmaxf(pAB, 0.0f) * fmaxf(pCB, 0.0f) * fmaxf(pCA, 0.0f); \
        float w1 = pCB * q3.x;                                               \
        float w2 = pCA * q3.x;                                               \
        float w3 = 1.0f - w1 - w2;                                           \
        float z  = w1 * q3.y + w2 * q3.z + w3 * q3.w;                        \
        bool take = (prod > 0.0f) &&                                         \
                    ((z > zb) || ((z == zb) && (off > bi)));                 \
        zb  = take ? z   : zb;                                               \
        bi  = take ? off : bi;                                               \
        w1s = take ? w1  : w1s;                                              \
        w2s = take ? w2  : w2s;                                              \
    }

    for (int k = slice; k < cnt; k += 8) {
        int offA = s_list[k];
        int offB = s_list[k + 4];
        EVAL(offA);
        EVAL(offB);
    }
    #undef EVAL

    // Merge the 4 slices of each pixel: (z, off) max, ties -> larger off.
    #pragma unroll
    for (int off = 8; off < 32; off <<= 1) {
        float oz = __shfl_down_sync(0xffffffffu, zb, off);
        int   oi = __shfl_down_sync(0xffffffffu, bi, off);
        float o1 = __shfl_down_sync(0xffffffffu, w1s, off);
        float o2 = __shfl_down_sync(0xffffffffu, w2s, off);
        bool take = (oz > zb) || ((oz == zb) && (oi > bi));
        if (take) { zb = oz; bi = oi; w1s = o1; w2s = o2; }
    }

    if (slice == 0) {
        // Deferred UV interpolation + bilinear texture sample (winner only)
        float r = 0.0f, g = 0.0f, b = 0.0f, a = 0.0f;
        if (bi >= 0) {
            a = 1.0f;
            const float* U = uvs + (bi / QSTRIDE) * 6;   // bi = tt*QSTRIDE
            float u0 = __ldg(U + 0) * 2.0f - 1.0f, v0 = __ldg(U + 1) * 2.0f - 1.0f;
            float u1 = __ldg(U + 2) * 2.0f - 1.0f, v1 = __ldg(U + 3) * 2.0f - 1.0f;
            float u2 = __ldg(U + 4) * 2.0f - 1.0f, v2 = __ldg(U + 5) * 2.0f - 1.0f;
            float w3 = 1.0f - w1s - w2s;
            float uu = w1s * u0 + w2s * u1 + w3 * u2;
            float vv = w1s * v0 + w2s * v1 + w3 * v2;

            float x = (uu + 1.0f) * 0.5f * 1023.0f;
            float y = (vv + 1.0f) * 0.5f * 1023.0f;
            float x0f = floorf(x);
            float y0f = floorf(y);
            float wx = x - x0f;
            float wy = y - y0f;
            #pragma unroll
            for (int cy = 0; cy < 2; cy++) {
                #pragma unroll
                for (int cx = 0; cx < 2; cx++) {
                    float ix = x0f + (float)cx;
                    float iy = y0f + (float)cy;
                    bool inb = (ix >= 0.0f) && (ix <= 1023.0f) &&
                               (iy >= 0.0f) && (iy <= 1023.0f);
                    if (inb) {
                        int ii = (int)ix;
                        int jj = (int)iy;
                        float wgt = (cx ? wx : 1.0f - wx) * (cy ? wy : 1.0f - wy);
                        int toff = jj * 1024 + ii;
                        r += __ldg(uvmap + toff) * wgt;
                        g += __ldg(uvmap + 1048576 + toff) * wgt;
                        b += __ldg(uvmap + 2097152 + toff) * wgt;
                    }
                }
            }
        }

        int pix = i * SZ + j;
        out[pix]              = r;
        out[65536 + pix]      = g;
        out[2 * 65536 + pix]  = b;
        out[3 * 65536 + pix]  = a;
    }
}

extern "C" void kernel_launch(void* const* d_in, const int* in_sizes, int n_in,
                              void* d_out, int out_size) {
    const float* tris  = (const float*)d_in[0];   // (256,3,3)
    const float* uvs   = (const float*)d_in[1];   // (256,3,2)
    const float* uvmap = (const float*)d_in[2];   // (3,1024,1024)
    float* out = (float*)d_out;                   // (4,256,256)

    dim3 block(256);
    dim3 grid(SZ / 8, SZ / 8);
    render_kernel<<<grid, block>>>(tris, uvs, uvmap, out);
}